// round 2
// baseline (speedup 1.0000x reference)
#include <cuda_runtime.h>
#include <float.h>

// Problem constants (fixed by the dataset)
#define N_  2
#define C_  256
#define H_  56
#define W_  56
#define R_  512
#define P_  7
#define SCALE_ 0.0625f

// Precomputed per-roi bin tables (scratch via __device__ globals — no allocs)
__device__ int g_hs[R_ * P_];
__device__ int g_he[R_ * P_];
__device__ int g_ws[R_ * P_];
__device__ int g_we[R_ * P_];
__device__ int g_b [R_];

__global__ void roi_precompute_kernel(const float* __restrict__ rois)
{
    int r = blockIdx.x * blockDim.x + threadIdx.x;
    if (r >= R_) return;

    const float* roi = rois + r * 5;
    int b  = (int)roi[0];                       // truncation, matches astype(int32)
    int x1 = __float2int_rn(roi[1] * SCALE_);   // round half-to-even == jnp.round
    int y1 = __float2int_rn(roi[2] * SCALE_);
    int x2 = __float2int_rn(roi[3] * SCALE_);
    int y2 = __float2int_rn(roi[4] * SCALE_);

    float bin_h = (float)max(y2 - y1 + 1, 1) * (1.0f / P_);
    float bin_w = (float)max(x2 - x1 + 1, 1) * (1.0f / P_);

    g_b[r] = b;
    #pragma unroll
    for (int p = 0; p < P_; ++p) {
        int hs = min(max((int)floorf((float)p       * bin_h) + y1, 0), H_);
        int he = min(max((int)ceilf ((float)(p + 1) * bin_h) + y1, 0), H_);
        int ws = min(max((int)floorf((float)p       * bin_w) + x1, 0), W_);
        int we = min(max((int)ceilf ((float)(p + 1) * bin_w) + x1, 0), W_);
        g_hs[r * P_ + p] = hs;
        g_he[r * P_ + p] = he;
        g_ws[r * P_ + p] = ws;
        g_we[r * P_ + p] = we;
    }
}

__global__ void roipool_kernel(const float* __restrict__ features,
                               float* __restrict__ out,
                               int total)
{
    int idx = blockIdx.x * blockDim.x + threadIdx.x;
    if (idx >= total) return;

    // Decode (r, c, ph, pw) from linear output index: out[r][c][ph][pw]
    int pw = idx % P_;
    int t  = idx / P_;
    int ph = t % P_;
    t /= P_;
    int c = t % C_;
    int r = t / C_;

    int hs = g_hs[r * P_ + ph];
    int he = g_he[r * P_ + ph];
    int ws = g_ws[r * P_ + pw];
    int we = g_we[r * P_ + pw];
    int b  = g_b[r];

    bool empty = (hs >= he) || (ws >= we);

    float m = -FLT_MAX;
    const float* plane = features + ((size_t)b * C_ + c) * (H_ * W_);
    for (int h = hs; h < he; ++h) {
        const float* row = plane + h * W_;
        for (int w = ws; w < we; ++w) {
            m = fmaxf(m, __ldg(row + w));
        }
    }

    out[idx] = empty ? 0.0f : m;
}

extern "C" void kernel_launch(void* const* d_in, const int* in_sizes, int n_in,
                              void* d_out, int out_size)
{
    const float* features = (const float*)d_in[0];
    const float* rois     = (const float*)d_in[1];
    float* out            = (float*)d_out;

    roi_precompute_kernel<<<1, R_>>>(rois);

    int total = out_size;  // R*C*P*P = 6,422,528
    int block = 256;
    int grid  = (total + block - 1) / block;
    roipool_kernel<<<grid, block>>>(features, out, total);
}

// round 3
// speedup vs baseline: 1.6890x; 1.6890x over previous
#include <cuda_runtime.h>
#include <float.h>

// Problem constants (fixed by the dataset)
#define N_  2
#define C_  256
#define H_  56
#define W_  56
#define R_  512
#define P_  7
#define SCALE_ 0.0625f
#define CHALF_ 128            // channels per thread-pass (thread does c and c+128)
#define PLANE_ (H_ * W_)

__global__ __launch_bounds__(256) void roipool_kernel(
    const float* __restrict__ features,
    const float* __restrict__ rois,
    float* __restrict__ out)
{
    int idx = blockIdx.x * blockDim.x + threadIdx.x;
    // idx decodes to (r, c in [0,128), ph, pw); thread handles c and c+128
    // total = R_ * CHALF_ * P_ * P_ = 3,211,264
    if (idx >= R_ * CHALF_ * P_ * P_) return;

    int pw = idx % P_;
    int t  = idx / P_;
    int ph = t % P_;
    t /= P_;
    int c = t % CHALF_;
    int r = t / CHALF_;

    // ---- inline ROI math (fp32, matches JAX semantics) ----
    const float* roi = rois + r * 5;
    int b  = (int)roi[0];                       // truncation == astype(int32)
    int x1 = __float2int_rn(roi[1] * SCALE_);   // round half-to-even == jnp.round
    int y1 = __float2int_rn(roi[2] * SCALE_);
    int x2 = __float2int_rn(roi[3] * SCALE_);
    int y2 = __float2int_rn(roi[4] * SCALE_);

    float bin_h = (float)max(y2 - y1 + 1, 1) * (1.0f / P_);
    float bin_w = (float)max(x2 - x1 + 1, 1) * (1.0f / P_);

    int hs = min(max((int)floorf((float)ph       * bin_h) + y1, 0), H_);
    int he = min(max((int)ceilf ((float)(ph + 1) * bin_h) + y1, 0), H_);
    int ws = min(max((int)floorf((float)pw       * bin_w) + x1, 0), W_);
    int we = min(max((int)ceilf ((float)(pw + 1) * bin_w) + x1, 0), W_);

    int dh = he - hs;
    int dw = we - ws;
    bool empty = (dh <= 0) || (dw <= 0);

    const float* planeA = features + ((size_t)b * C_ + c) * PLANE_;
    const float* planeB = planeA + (size_t)CHALF_ * PLANE_;

    float mA = -FLT_MAX;
    float mB = -FLT_MAX;

    if (dh <= 4 && dw <= 4) {
        // ---- fast path: branchless predicated 4x4 window, MLP = 32 ----
        const float* baseA = planeA + hs * W_ + ws;
        const float* baseB = planeB + hs * W_ + ws;
        #pragma unroll
        for (int i = 0; i < 4; ++i) {
            bool vi = (i < dh);
            #pragma unroll
            for (int j = 0; j < 4; ++j) {
                bool v = vi && (j < dw);
                if (v) {
                    mA = fmaxf(mA, __ldg(baseA + i * W_ + j));
                    mB = fmaxf(mB, __ldg(baseB + i * W_ + j));
                }
            }
        }
    } else {
        // ---- rare fallback: window wider than 4 (span can reach 5) ----
        for (int h = hs; h < he; ++h) {
            const float* rowA = planeA + h * W_;
            const float* rowB = planeB + h * W_;
            for (int w = ws; w < we; ++w) {
                mA = fmaxf(mA, __ldg(rowA + w));
                mB = fmaxf(mB, __ldg(rowB + w));
            }
        }
    }

    // output layout: out[r][c][ph][pw], C_=256
    size_t o = (((size_t)r * C_ + c) * P_ + ph) * P_ + pw;
    out[o]                            = empty ? 0.0f : mA;
    out[o + (size_t)CHALF_ * P_ * P_] = empty ? 0.0f : mB;
}

extern "C" void kernel_launch(void* const* d_in, const int* in_sizes, int n_in,
                              void* d_out, int out_size)
{
    const float* features = (const float*)d_in[0];
    const float* rois     = (const float*)d_in[1];
    float* out            = (float*)d_out;

    int total = R_ * CHALF_ * P_ * P_;  // 3,211,264 threads, 2 outputs each
    int block = 256;
    int grid  = (total + block - 1) / block;
    roipool_kernel<<<grid, block>>>(features, rois, out);
}